// round 1
// baseline (speedup 1.0000x reference)
#include <cuda_runtime.h>

// ---------------- problem constants (deterministic inputs) ----------------
#define B_    64
#define NTOK  4096
#define NSEQ  2048     // n
#define XD    256      // x_dim
#define HD    512      // Hd (hidden width)
#define H2    256      // h_dim
#define GD    512      // g_dim
#define KC    32       // clusters K
#define NG    65       // 2K+1
#define NE    33       // K+1

// ---------------- scratch (__device__ globals, no allocs) ----------------
__device__ float g_Ah[(size_t)B_ * NSEQ * HD];        // relu(x Wh1 + bh1), tokens 0..2047
__device__ float g_Aq[(size_t)B_ * (NSEQ - 1) * HD];  // relu(x Wq1 + bq1), tokens 2049..4095 (2047 rows/batch)
__device__ float g_xn[B_ * XD];
__device__ float g_hn1[B_ * HD];
__device__ float g_hn[B_ * H2];
__device__ float g_Hsum[B_ * KC * HD];
__device__ float g_Qpart[B_ * 16 * HD];
__device__ float g_Qsum[B_ * HD];
__device__ float g_Hk2[B_ * KC * H2];   // Hsum @ Wh2 (bias added later with cnt scaling)
__device__ float g_Q2[B_ * H2];         // Qsum @ Wq2 (bias added later * 2047)
__device__ float g_Hmat[B_ * NG * H2];
__device__ float g_g1[B_ * NG * HD];
__device__ float g_gs[B_ * NG * GD];
__device__ float g_S[B_ * GD];
__device__ float g_uu[B_ * NE * (GD + H2)];
__device__ float g_e1[B_ * NE * HD];
__device__ int   g_tok[NSEQ];
__device__ int   g_start[KC + 1];
__device__ int   g_cnt[KC];

// ---------------- generic fp32 tiled GEMM: C = [relu](A @ W [+ bias]) ------
// A: [M,K] row-major (lda = K), W: [K,N] row-major, C: [M,N] row-major.
// N multiple of 128, K multiple of 16. M guarded. blockIdx.z batches A/C.
template <int RELU, int HASBIAS>
__global__ __launch_bounds__(256, 2)
void sgemm(const float* __restrict__ A, const float* __restrict__ W,
           const float* __restrict__ bias, float* __restrict__ C,
           int M, int N, int K, long long strideA, long long strideC)
{
    A += (long long)blockIdx.z * strideA;
    C += (long long)blockIdx.z * strideC;

    __shared__ float As[16][128];   // transposed A tile: As[k][m]
    __shared__ float Bs[16][128];

    const int tid = threadIdx.x;
    const int tx = tid & 15;        // 16 col-groups * 8 cols
    const int ty = tid >> 4;        // 16 row-groups * 8 rows
    const int n0 = blockIdx.x * 128;
    const int m0 = blockIdx.y * 128;

    float acc[8][8];
#pragma unroll
    for (int i = 0; i < 8; i++)
#pragma unroll
        for (int j = 0; j < 8; j++) acc[i][j] = 0.f;

    for (int k0 = 0; k0 < K; k0 += 16) {
        // A tile: 512 float4 loads, transposed into As
#pragma unroll
        for (int it = 0; it < 2; it++) {
            int lin = it * 256 + tid;           // float4 index
            int m   = lin >> 2;                 // 4 float4 per row
            int kq  = (lin & 3) * 4;
            float4 v = make_float4(0.f, 0.f, 0.f, 0.f);
            if (m0 + m < M)
                v = *(const float4*)(A + (long long)(m0 + m) * K + k0 + kq);
            As[kq + 0][m] = v.x; As[kq + 1][m] = v.y;
            As[kq + 2][m] = v.z; As[kq + 3][m] = v.w;
        }
        // B tile: row-major straight copy
#pragma unroll
        for (int it = 0; it < 2; it++) {
            int lin = it * 256 + tid;
            int k   = lin >> 5;                 // 32 float4 per row
            int nq  = (lin & 31) * 4;
            *(float4*)&Bs[k][nq] =
                *(const float4*)(W + (long long)(k0 + k) * N + n0 + nq);
        }
        __syncthreads();

#pragma unroll
        for (int kk = 0; kk < 16; kk++) {
            float a[8], b[8];
            *(float4*)(a)     = *(float4*)&As[kk][ty * 8];
            *(float4*)(a + 4) = *(float4*)&As[kk][ty * 8 + 4];
            *(float4*)(b)     = *(float4*)&Bs[kk][tx * 8];
            *(float4*)(b + 4) = *(float4*)&Bs[kk][tx * 8 + 4];
#pragma unroll
            for (int i = 0; i < 8; i++)
#pragma unroll
                for (int j = 0; j < 8; j++)
                    acc[i][j] = fmaf(a[i], b[j], acc[i][j]);
        }
        __syncthreads();
    }

    // epilogue
    float bi[8];
    if (HASBIAS) {
        *(float4*)(bi)     = *(const float4*)(bias + n0 + tx * 8);
        *(float4*)(bi + 4) = *(const float4*)(bias + n0 + tx * 8 + 4);
    }
#pragma unroll
    for (int i = 0; i < 8; i++) {
        int m = m0 + ty * 8 + i;
        if (m < M) {
            float out[8];
#pragma unroll
            for (int j = 0; j < 8; j++) {
                float v = acc[i][j];
                if (HASBIAS) v += bi[j];
                if (RELU) v = fmaxf(v, 0.f);
                out[j] = v;
            }
            float* cp = C + (long long)m * N + n0 + tx * 8;
            *(float4*)(cp)     = *(float4*)(out);
            *(float4*)(cp + 4) = *(float4*)(out + 4);
        }
    }
}

// ------------- setup: counting-sort cs[0,:n] by cluster; gather x_n --------
__global__ void k_setup(const int* __restrict__ cs, const float* __restrict__ data)
{
    __shared__ int scnt[KC];
    __shared__ int soff[KC];
    int tid = threadIdx.x;
    if (tid < KC) scnt[tid] = 0;
    __syncthreads();
    for (int t = tid; t < NSEQ; t += 256) atomicAdd(&scnt[cs[t]], 1);
    __syncthreads();
    if (tid == 0) {
        int acc = 0;
        for (int k = 0; k < KC; k++) {
            g_start[k] = acc; soff[k] = acc; g_cnt[k] = scnt[k];
            acc += scnt[k];
        }
        g_start[KC] = acc;
    }
    __syncthreads();
    for (int t = tid; t < NSEQ; t += 256) {
        int p = atomicAdd(&soff[cs[t]], 1);
        g_tok[p] = t;
    }
    // gather token n per batch
    for (int i = tid; i < B_ * XD; i += 256) {
        int b = i >> 8, c = i & 255;
        g_xn[i] = data[((long long)b * NTOK + NSEQ) * XD + c];
    }
}

// ------------- cluster reduction: Hsum[b,k,:] = sum rows of g_Ah -----------
__global__ void k_reduce_h()
{
    int k = blockIdx.x, b = blockIdx.y, tid = threadIdx.x;   // 256 threads
    int s = g_start[k], e = g_start[k + 1];
    const float* base = g_Ah + (long long)b * NSEQ * HD;
    float a0 = 0.f, a1 = 0.f;
    for (int t = s; t < e; t++) {
        const float* r = base + (long long)g_tok[t] * HD;
        a0 += r[tid];
        a1 += r[tid + 256];
    }
    float* o = g_Hsum + (long long)(b * KC + k) * HD;
    o[tid] = a0; o[tid + 256] = a1;
}

// ------------- q reduction (partials over 16 row-chunks) -------------------
__global__ void k_reduce_q()
{
    int c = blockIdx.x, b = blockIdx.y, tid = threadIdx.x;   // 512 threads
    int r0 = c * 128;
    int r1 = min(r0 + 128, NSEQ - 1);                        // 2047 rows
    const float* base = g_Aq + (long long)b * (NSEQ - 1) * HD;
    float a = 0.f;
    for (int r = r0; r < r1; r++) a += base[(long long)r * HD + tid];
    g_Qpart[((long long)b * 16 + c) * HD + tid] = a;
}

__global__ void k_reduce_q2()
{
    int b = blockIdx.x, tid = threadIdx.x;                   // 512 threads
    float a = 0.f;
    for (int c = 0; c < 16; c++) a += g_Qpart[((long long)b * 16 + c) * HD + tid];
    g_Qsum[(long long)b * HD + tid] = a;
}

// ------------- build H matrix (input rows to g-MLP) ------------------------
__global__ void k_buildH(const float* __restrict__ bh2)
{
    int i = blockIdx.x, b = blockIdx.y, j = threadIdx.x;     // 256 threads
    float hnv = g_hn[b * H2 + j];
    float v;
    if (i < KC) {
        v = g_Hk2[(b * KC + i) * H2 + j] + (float)g_cnt[i] * bh2[j];
    } else if (i < 2 * KC) {
        int k = i - KC;
        v = g_Hk2[(b * KC + k) * H2 + j] + (float)g_cnt[k] * bh2[j] + hnv;
    } else {
        v = hnv;
    }
    g_Hmat[((long long)b * NG + i) * H2 + j] = v;
}

// ------------- S[b,:] = sum_{k<K} gs[b,k,:] --------------------------------
__global__ void k_S()
{
    int b = blockIdx.x, j = threadIdx.x;                     // 512 threads
    float a = 0.f;
    for (int k = 0; k < KC; k++) a += g_gs[((long long)b * NG + k) * GD + j];
    g_S[b * GD + j] = a;
}

// ------------- build uu rows (G concat broadcast Q) ------------------------
__global__ void k_builduu(const float* __restrict__ bq2)
{
    int i = blockIdx.x, b = blockIdx.y, tid = threadIdx.x;   // 256 threads
    long long row = (long long)b * NE + i;
    float* u = g_uu + row * (GD + H2);
    for (int j = tid; j < GD; j += 256) {
        float s = g_S[b * GD + j];
        float v;
        if (i < KC)
            v = s - g_gs[((long long)b * NG + i) * GD + j]
                  + g_gs[((long long)b * NG + KC + i) * GD + j];
        else
            v = s + g_gs[((long long)b * NG + 2 * KC) * GD + j];
        u[j] = v;
    }
    // Q block (h_dim = 256 == blockDim)
    u[GD + tid] = g_Q2[b * H2 + tid] + 2047.0f * bq2[tid];
}

// ------------- final: E = e1 @ We2 (512 -> 1), plus mask -------------------
__global__ void k_E(const float* __restrict__ We2, float* __restrict__ out)
{
    int row = blockIdx.x * 4 + (threadIdx.x >> 5);
    int lane = threadIdx.x & 31;
    if (row >= B_ * NE) return;
    const float* e = g_e1 + (long long)row * HD;
    float a = 0.f;
    for (int j = lane; j < HD; j += 32) a += e[j] * We2[j];
#pragma unroll
    for (int o = 16; o > 0; o >>= 1) a += __shfl_xor_sync(0xFFFFFFFFu, a, o);
    if (lane == 0) {
        out[row] = a;                  // E
        out[B_ * NE + row] = 1.0f;     // G_mask (all ones)
    }
}

// ---------------------------------------------------------------------------
extern "C" void kernel_launch(void* const* d_in, const int* in_sizes, int n_in,
                              void* d_out, int out_size)
{
    const float* data = (const float*)d_in[0];
    const int*   cs   = (const int*)  d_in[1];
    // d_in[2] = n (2048, deterministic)
    const float* Wh1 = (const float*)d_in[3];
    const float* bh1 = (const float*)d_in[4];
    const float* Wh2 = (const float*)d_in[5];
    const float* bh2 = (const float*)d_in[6];
    const float* Wq1 = (const float*)d_in[7];
    const float* bq1 = (const float*)d_in[8];
    const float* Wq2 = (const float*)d_in[9];
    const float* bq2 = (const float*)d_in[10];
    const float* Wg1 = (const float*)d_in[11];
    const float* bg1 = (const float*)d_in[12];
    const float* Wg2 = (const float*)d_in[13];
    const float* bg2 = (const float*)d_in[14];
    const float* We1 = (const float*)d_in[15];
    const float* be1 = (const float*)d_in[16];
    const float* We2 = (const float*)d_in[17];
    float* out = (float*)d_out;

    float *p_Ah, *p_Aq, *p_xn, *p_hn1, *p_hn, *p_Hsum, *p_Qsum, *p_Hk2, *p_Q2;
    float *p_Hmat, *p_g1, *p_gs, *p_uu, *p_e1;
    cudaGetSymbolAddress((void**)&p_Ah, g_Ah);
    cudaGetSymbolAddress((void**)&p_Aq, g_Aq);
    cudaGetSymbolAddress((void**)&p_xn, g_xn);
    cudaGetSymbolAddress((void**)&p_hn1, g_hn1);
    cudaGetSymbolAddress((void**)&p_hn, g_hn);
    cudaGetSymbolAddress((void**)&p_Hsum, g_Hsum);
    cudaGetSymbolAddress((void**)&p_Qsum, g_Qsum);
    cudaGetSymbolAddress((void**)&p_Hk2, g_Hk2);
    cudaGetSymbolAddress((void**)&p_Q2, g_Q2);
    cudaGetSymbolAddress((void**)&p_Hmat, g_Hmat);
    cudaGetSymbolAddress((void**)&p_g1, g_g1);
    cudaGetSymbolAddress((void**)&p_gs, g_gs);
    cudaGetSymbolAddress((void**)&p_uu, g_uu);
    cudaGetSymbolAddress((void**)&p_e1, g_e1);

    // 0) sort clusters + gather x_n
    k_setup<<<1, 256>>>(cs, data);

    // 1) first layer, h-region: tokens 0..2047 of every batch
    sgemm<1, 1><<<dim3(HD / 128, NSEQ / 128, B_), 256>>>(
        data, Wh1, bh1, p_Ah, NSEQ, HD, XD,
        (long long)NTOK * XD, (long long)NSEQ * HD);

    // 2) first layer, q-region: tokens 2049..4095 (2047 rows/batch)
    sgemm<1, 1><<<dim3(HD / 128, (NSEQ - 1 + 127) / 128, B_), 256>>>(
        data + (long long)(NSEQ + 1) * XD, Wq1, bq1, p_Aq, NSEQ - 1, HD, XD,
        (long long)NTOK * XD, (long long)(NSEQ - 1) * HD);

    // 3) hn: full h-MLP for token n of each batch
    sgemm<1, 1><<<dim3(HD / 128, 1, 1), 256>>>(p_xn, Wh1, bh1, p_hn1, B_, HD, XD, 0, 0);
    sgemm<0, 1><<<dim3(H2 / 128, 1, 1), 256>>>(p_hn1, Wh2, bh2, p_hn, B_, H2, HD, 0, 0);

    // 4) cluster sums + q sum
    k_reduce_h<<<dim3(KC, B_), 256>>>();
    k_reduce_q<<<dim3(16, B_), 512>>>();
    k_reduce_q2<<<B_, 512>>>();

    // 5) second layers on the *summed* activations (linearity of layer 2)
    sgemm<0, 0><<<dim3(H2 / 128, (B_ * KC) / 128, 1), 256>>>(
        p_Hsum, Wh2, nullptr, p_Hk2, B_ * KC, H2, HD, 0, 0);
    sgemm<0, 0><<<dim3(H2 / 128, 1, 1), 256>>>(
        p_Qsum, Wq2, nullptr, p_Q2, B_, H2, HD, 0, 0);

    // 6) build H rows, g-MLP
    k_buildH<<<dim3(NG, B_), H2>>>(bh2);
    sgemm<1, 1><<<dim3(HD / 128, (B_ * NG + 127) / 128, 1), 256>>>(
        p_Hmat, Wg1, bg1, p_g1, B_ * NG, HD, H2, 0, 0);
    sgemm<0, 1><<<dim3(GD / 128, (B_ * NG + 127) / 128, 1), 256>>>(
        p_g1, Wg2, bg2, p_gs, B_ * NG, GD, HD, 0, 0);

    // 7) S, uu, e-MLP, E + mask
    k_S<<<B_, GD>>>();
    k_builduu<<<dim3(NE, B_), 256>>>(bq2);
    sgemm<1, 1><<<dim3(HD / 128, (B_ * NE + 127) / 128, 1), 256>>>(
        p_uu, We1, be1, p_e1, B_ * NE, HD, GD + H2, 0, 0);
    k_E<<<(B_ * NE + 3) / 4, 128>>>(We2, out);
}

// round 3
// speedup vs baseline: 2.1089x; 2.1089x over previous
#include <cuda_runtime.h>
#include <cstdint>

// ---------------- problem constants (deterministic inputs) ----------------
#define B_    64
#define NTOK  4096
#define NSEQ  2048     // n
#define XD    256      // x_dim
#define HD    512      // Hd (hidden width)
#define H2    256      // h_dim
#define GD    512      // g_dim
#define KC    32       // clusters K
#define NG    65       // 2K+1
#define NE    33       // K+1

// ---------------- scratch (__device__ globals, no allocs) ----------------
__device__ float g_Ah[(size_t)B_ * NSEQ * HD];
__device__ float g_Aq[(size_t)B_ * (NSEQ - 1) * HD];
__device__ float g_WhT[HD * XD];                      // Wh1^T, tf32-rounded, [N=512][K=256]
__device__ float g_WqT[HD * XD];
__device__ float g_xn[B_ * XD];
__device__ float g_hn1[B_ * HD];
__device__ float g_hn[B_ * H2];
__device__ float g_Hsum[B_ * KC * HD];
__device__ float g_Qpart[B_ * 16 * HD];
__device__ float g_Qsum[B_ * HD];
__device__ float g_Hk2[B_ * KC * H2];
__device__ float g_Q2[B_ * H2];
__device__ float g_Hmat[B_ * NG * H2];
__device__ float g_g1[B_ * NG * HD];
__device__ float g_gs[B_ * NG * GD];
__device__ float g_S[B_ * GD];
__device__ float g_uu[B_ * NE * (GD + H2)];
__device__ float g_e1[B_ * NE * HD];
__device__ int   g_tok[NSEQ];
__device__ int   g_start[KC + 1];
__device__ int   g_cnt[KC];

// =======================================================================
//  tf32 mma.sync GEMM:  C[M,512] = relu(A[M,256] @ W + bias)
//  A fp32 row-major (lda=256). WT = W^T tf32-rounded, [512][256] row-major
//  (= B col-major for mma row.col). CTA tile 128x128, 8 warps (2m x 4n),
//  warp tile 64x32, K chunks of 32, 3-stage cp.async pipeline.
// =======================================================================
#define BM 128
#define BN 128
#define BK 32
#define NCHUNK 8                       // 256 / 32
#define STAGE_BYTES (BM * 128 + BN * 128)   // 32768
#define SMEM_GEMM (3 * STAGE_BYTES)         // 98304

__device__ __forceinline__ uint32_t s2u(const void* p) {
    uint32_t a;
    asm("{ .reg .u64 t; cvta.to.shared.u64 t, %1; cvt.u32.u64 %0, t; }" : "=r"(a) : "l"(p));
    return a;
}
__device__ __forceinline__ void cp16(uint32_t dst, const void* src, uint32_t sz) {
    asm volatile("cp.async.cg.shared.global [%0], [%1], 16, %2;\n" :: "r"(dst), "l"(src), "r"(sz));
}
__device__ __forceinline__ void cp_commit() {
    asm volatile("cp.async.commit_group;" ::: "memory");
}
template <int N>
__device__ __forceinline__ void cp_wait() {
    asm volatile("cp.async.wait_group %0;" :: "n"(N) : "memory");
}
__device__ __forceinline__ void ldsm4(uint32_t* r, uint32_t addr) {
    asm volatile("ldmatrix.sync.aligned.m8n8.x4.shared.b16 {%0,%1,%2,%3}, [%4];"
                 : "=r"(r[0]), "=r"(r[1]), "=r"(r[2]), "=r"(r[3]) : "r"(addr));
}
__device__ __forceinline__ void mma_tf32(float* d, const uint32_t* a, uint32_t b0, uint32_t b1) {
    asm volatile(
        "mma.sync.aligned.m16n8k8.row.col.f32.tf32.tf32.f32 "
        "{%0,%1,%2,%3}, {%4,%5,%6,%7}, {%8,%9}, {%0,%1,%2,%3};"
        : "+f"(d[0]), "+f"(d[1]), "+f"(d[2]), "+f"(d[3])
        : "r"(a[0]), "r"(a[1]), "r"(a[2]), "r"(a[3]), "r"(b0), "r"(b1));
}

__global__ __launch_bounds__(256, 2)
void tc_gemm(const float* __restrict__ A, const float* __restrict__ WT,
             const float* __restrict__ bias, float* __restrict__ C,
             int M, long long strideA, long long strideC)
{
    extern __shared__ char smem[];
    const int tid = threadIdx.x, wid = tid >> 5, lane = tid & 31;
    const int warpM = wid & 1, warpN = wid >> 1;
    const int m0 = blockIdx.x * BM, n0 = blockIdx.y * BN;
    A += (long long)blockIdx.z * strideA;
    C += (long long)blockIdx.z * strideC;
    const char* Ab = (const char*)A;
    const char* Bb = (const char*)(WT + (long long)n0 * XD);
    const uint32_t sb = s2u(smem);

    float acc[4][4][4];
#pragma unroll
    for (int i = 0; i < 4; i++)
#pragma unroll
        for (int j = 0; j < 4; j++)
#pragma unroll
            for (int q = 0; q < 4; q++) acc[i][j][q] = 0.f;

    // ldmatrix per-lane geometry
    const int t = lane >> 3, r8 = lane & 7;
    // A: x4 tile covers one 16x8k m-tile: tiles (rows0-7,kLo),(rows8-15,kLo),(rows0-7,kHi),(rows8-15,kHi)
    int rowA[4];
#pragma unroll
    for (int mt = 0; mt < 4; mt++) rowA[mt] = warpM * 64 + mt * 16 + (t & 1) * 8 + r8;
    const int thalfA = t >> 1;
    // B: x4 covers n-tile pair p: (n0-7,kLo),(n0-7,kHi),(n8-15,kLo),(n8-15,kHi)
    int rowB[2];
#pragma unroll
    for (int p = 0; p < 2; p++) rowB[p] = warpN * 32 + p * 16 + (t >> 1) * 8 + r8;
    const int thalfB = t & 1;

#define LOAD_CHUNK(c, stg) do {                                               \
        uint32_t as_ = sb + (stg) * STAGE_BYTES;                              \
        uint32_t bs_ = as_ + BM * 128;                                        \
        int k0b_ = (c) * BK * 4;                                              \
        _Pragma("unroll")                                                     \
        for (int it = 0; it < 4; it++) {                                      \
            int g_ = it * 256 + tid;                                          \
            int row_ = g_ >> 3, c16_ = g_ & 7;                                \
            uint32_t dst_ = as_ + row_ * 128 + (((uint32_t)(c16_ ^ (row_ & 7))) << 4); \
            cp16(dst_, Ab + (long long)(m0 + row_) * 1024 + k0b_ + c16_ * 16, \
                 (m0 + row_) < M ? 16u : 0u);                                 \
        }                                                                     \
        _Pragma("unroll")                                                     \
        for (int it = 0; it < 4; it++) {                                      \
            int g_ = it * 256 + tid;                                          \
            int row_ = g_ >> 3, c16_ = g_ & 7;                                \
            uint32_t dst_ = bs_ + row_ * 128 + (((uint32_t)(c16_ ^ (row_ & 7))) << 4); \
            cp16(dst_, Bb + (long long)row_ * 1024 + k0b_ + c16_ * 16, 16u);  \
        }                                                                     \
        cp_commit();                                                          \
    } while (0)

    LOAD_CHUNK(0, 0);
    LOAD_CHUNK(1, 1);

    for (int c = 0; c < NCHUNK; c++) {
        if (c < NCHUNK - 1) cp_wait<1>(); else cp_wait<0>();
        __syncthreads();
        if (c + 2 < NCHUNK) LOAD_CHUNK(c + 2, (c + 2) % 3);

        const int stg = c % 3;
        const uint32_t as = sb + stg * STAGE_BYTES;
        const uint32_t bs = as + BM * 128;

#pragma unroll
        for (int kk = 0; kk < 4; kk++) {
            uint32_t af[4][4];
#pragma unroll
            for (int mt = 0; mt < 4; mt++) {
                uint32_t addr = as + rowA[mt] * 128 +
                                (((uint32_t)((kk * 2 + thalfA) ^ (rowA[mt] & 7))) << 4);
                ldsm4(af[mt], addr);
#pragma unroll
                for (int q = 0; q < 4; q++)
                    asm("cvt.rna.tf32.f32 %0, %0;" : "+r"(af[mt][q]));
            }
            uint32_t bf[2][4];
#pragma unroll
            for (int p = 0; p < 2; p++) {
                uint32_t addr = bs + rowB[p] * 128 +
                                (((uint32_t)((kk * 2 + thalfB) ^ (rowB[p] & 7))) << 4);
                ldsm4(bf[p], addr);
            }
#pragma unroll
            for (int mt = 0; mt < 4; mt++) {
#pragma unroll
                for (int nt = 0; nt < 4; nt++) {
                    const uint32_t* bp = bf[nt >> 1];
                    mma_tf32(acc[mt][nt], af[mt],
                             bp[(nt & 1) * 2], bp[(nt & 1) * 2 + 1]);
                }
            }
        }
    }

    // epilogue: bias + relu + store (c0,c1 = row g cols 2tig..; c2,c3 = row g+8)
    const int g = lane >> 2, tig = lane & 3;
#pragma unroll
    for (int nt = 0; nt < 4; nt++) {
        int col = n0 + warpN * 32 + nt * 8 + tig * 2;
        float2 bv = *(const float2*)(bias + col);
#pragma unroll
        for (int mt = 0; mt < 4; mt++) {
            int row = m0 + warpM * 64 + mt * 16 + g;
            if (row < M) {
                float2 o;
                o.x = fmaxf(acc[mt][nt][0] + bv.x, 0.f);
                o.y = fmaxf(acc[mt][nt][1] + bv.y, 0.f);
                *(float2*)(C + (long long)row * HD + col) = o;
            }
            if (row + 8 < M) {
                float2 o;
                o.x = fmaxf(acc[mt][nt][2] + bv.x, 0.f);
                o.y = fmaxf(acc[mt][nt][3] + bv.y, 0.f);
                *(float2*)(C + (long long)(row + 8) * HD + col) = o;
            }
        }
    }
#undef LOAD_CHUNK
}

// ------------- W transpose + tf32 rounding ---------------------------------
__global__ void k_prepW(const float* __restrict__ Wh1, const float* __restrict__ Wq1)
{
    int i = blockIdx.x * 256 + threadIdx.x;
    if (i < HD * XD) {
        int nn = i >> 8, kk = i & 255;
        uint32_t a, b;
        asm("cvt.rna.tf32.f32 %0, %1;" : "=r"(a) : "f"(Wh1[kk * HD + nn]));
        asm("cvt.rna.tf32.f32 %0, %1;" : "=r"(b) : "f"(Wq1[kk * HD + nn]));
        ((uint32_t*)g_WhT)[i] = a;
        ((uint32_t*)g_WqT)[i] = b;
    }
}

// ---------------- generic fp32 tiled GEMM (small ops) ----------------------
template <int RELU, int HASBIAS>
__global__ __launch_bounds__(256, 2)
void sgemm(const float* __restrict__ A, const float* __restrict__ W,
           const float* __restrict__ bias, float* __restrict__ C,
           int M, int N, int K, long long strideA, long long strideC)
{
    A += (long long)blockIdx.z * strideA;
    C += (long long)blockIdx.z * strideC;

    __shared__ float As[16][128];
    __shared__ float Bs[16][128];

    const int tid = threadIdx.x;
    const int tx = tid & 15;
    const int ty = tid >> 4;
    const int n0 = blockIdx.x * 128;
    const int m0 = blockIdx.y * 128;

    float acc[8][8];
#pragma unroll
    for (int i = 0; i < 8; i++)
#pragma unroll
        for (int j = 0; j < 8; j++) acc[i][j] = 0.f;

    for (int k0 = 0; k0 < K; k0 += 16) {
#pragma unroll
        for (int it = 0; it < 2; it++) {
            int lin = it * 256 + tid;
            int m   = lin >> 2;
            int kq  = (lin & 3) * 4;
            float4 v = make_float4(0.f, 0.f, 0.f, 0.f);
            if (m0 + m < M)
                v = *(const float4*)(A + (long long)(m0 + m) * K + k0 + kq);
            As[kq + 0][m] = v.x; As[kq + 1][m] = v.y;
            As[kq + 2][m] = v.z; As[kq + 3][m] = v.w;
        }
#pragma unroll
        for (int it = 0; it < 2; it++) {
            int lin = it * 256 + tid;
            int k   = lin >> 5;
            int nq  = (lin & 31) * 4;
            *(float4*)&Bs[k][nq] =
                *(const float4*)(W + (long long)(k0 + k) * N + n0 + nq);
        }
        __syncthreads();

#pragma unroll
        for (int kk = 0; kk < 16; kk++) {
            float a[8], b[8];
            *(float4*)(a)     = *(float4*)&As[kk][ty * 8];
            *(float4*)(a + 4) = *(float4*)&As[kk][ty * 8 + 4];
            *(float4*)(b)     = *(float4*)&Bs[kk][tx * 8];
            *(float4*)(b + 4) = *(float4*)&Bs[kk][tx * 8 + 4];
#pragma unroll
            for (int i = 0; i < 8; i++)
#pragma unroll
                for (int j = 0; j < 8; j++)
                    acc[i][j] = fmaf(a[i], b[j], acc[i][j]);
        }
        __syncthreads();
    }

    float bi[8];
    if (HASBIAS) {
        *(float4*)(bi)     = *(const float4*)(bias + n0 + tx * 8);
        *(float4*)(bi + 4) = *(const float4*)(bias + n0 + tx * 8 + 4);
    }
#pragma unroll
    for (int i = 0; i < 8; i++) {
        int m = m0 + ty * 8 + i;
        if (m < M) {
            float out[8];
#pragma unroll
            for (int j = 0; j < 8; j++) {
                float v = acc[i][j];
                if (HASBIAS) v += bi[j];
                if (RELU) v = fmaxf(v, 0.f);
                out[j] = v;
            }
            float* cp = C + (long long)m * N + n0 + tx * 8;
            *(float4*)(cp)     = *(float4*)(out);
            *(float4*)(cp + 4) = *(float4*)(out + 4);
        }
    }
}

// ------------- setup: counting-sort cs[0,:n] by cluster; gather x_n --------
__global__ void k_setup(const int* __restrict__ cs, const float* __restrict__ data)
{
    __shared__ int scnt[KC];
    __shared__ int soff[KC];
    int tid = threadIdx.x;
    if (tid < KC) scnt[tid] = 0;
    __syncthreads();
    for (int t = tid; t < NSEQ; t += 256) atomicAdd(&scnt[cs[t]], 1);
    __syncthreads();
    if (tid == 0) {
        int acc = 0;
        for (int k = 0; k < KC; k++) {
            g_start[k] = acc; soff[k] = acc; g_cnt[k] = scnt[k];
            acc += scnt[k];
        }
        g_start[KC] = acc;
    }
    __syncthreads();
    for (int t = tid; t < NSEQ; t += 256) {
        int p = atomicAdd(&soff[cs[t]], 1);
        g_tok[p] = t;
    }
    for (int i = tid; i < B_ * XD; i += 256) {
        int b = i >> 8, c = i & 255;
        g_xn[i] = data[((long long)b * NTOK + NSEQ) * XD + c];
    }
}

// ------------- cluster reduction ------------------------------------------
__global__ void k_reduce_h()
{
    int k = blockIdx.x, b = blockIdx.y, tid = threadIdx.x;
    int s = g_start[k], e = g_start[k + 1];
    const float* base = g_Ah + (long long)b * NSEQ * HD;
    float a0 = 0.f, a1 = 0.f;
    for (int t = s; t < e; t++) {
        const float* r = base + (long long)g_tok[t] * HD;
        a0 += r[tid];
        a1 += r[tid + 256];
    }
    float* o = g_Hsum + (long long)(b * KC + k) * HD;
    o[tid] = a0; o[tid + 256] = a1;
}

__global__ void k_reduce_q()
{
    int c = blockIdx.x, b = blockIdx.y, tid = threadIdx.x;
    int r0 = c * 128;
    int r1 = min(r0 + 128, NSEQ - 1);
    const float* base = g_Aq + (long long)b * (NSEQ - 1) * HD;
    float a = 0.f;
    for (int r = r0; r < r1; r++) a += base[(long long)r * HD + tid];
    g_Qpart[((long long)b * 16 + c) * HD + tid] = a;
}

__global__ void k_reduce_q2()
{
    int b = blockIdx.x, tid = threadIdx.x;
    float a = 0.f;
    for (int c = 0; c < 16; c++) a += g_Qpart[((long long)b * 16 + c) * HD + tid];
    g_Qsum[(long long)b * HD + tid] = a;
}

// ------------- build H matrix ---------------------------------------------
__global__ void k_buildH(const float* __restrict__ bh2)
{
    int i = blockIdx.x, b = blockIdx.y, j = threadIdx.x;
    float hnv = g_hn[b * H2 + j];
    float v;
    if (i < KC) {
        v = g_Hk2[(b * KC + i) * H2 + j] + (float)g_cnt[i] * bh2[j];
    } else if (i < 2 * KC) {
        int k = i - KC;
        v = g_Hk2[(b * KC + k) * H2 + j] + (float)g_cnt[k] * bh2[j] + hnv;
    } else {
        v = hnv;
    }
    g_Hmat[((long long)b * NG + i) * H2 + j] = v;
}

__global__ void k_S()
{
    int b = blockIdx.x, j = threadIdx.x;
    float a = 0.f;
    for (int k = 0; k < KC; k++) a += g_gs[((long long)b * NG + k) * GD + j];
    g_S[b * GD + j] = a;
}

__global__ void k_builduu(const float* __restrict__ bq2)
{
    int i = blockIdx.x, b = blockIdx.y, tid = threadIdx.x;
    long long row = (long long)b * NE + i;
    float* u = g_uu + row * (GD + H2);
    for (int j = tid; j < GD; j += 256) {
        float s = g_S[b * GD + j];
        float v;
        if (i < KC)
            v = s - g_gs[((long long)b * NG + i) * GD + j]
                  + g_gs[((long long)b * NG + KC + i) * GD + j];
        else
            v = s + g_gs[((long long)b * NG + 2 * KC) * GD + j];
        u[j] = v;
    }
    u[GD + tid] = g_Q2[b * H2 + tid] + 2047.0f * bq2[tid];
}

__global__ void k_E(const float* __restrict__ We2, float* __restrict__ out)
{
    int row = blockIdx.x * 4 + (threadIdx.x >> 5);
    int lane = threadIdx.x & 31;
    if (row >= B_ * NE) return;
    const float* e = g_e1 + (long long)row * HD;
    float a = 0.f;
    for (int j = lane; j < HD; j += 32) a += e[j] * We2[j];
#pragma unroll
    for (int o = 16; o > 0; o >>= 1) a += __shfl_xor_sync(0xFFFFFFFFu, a, o);
    if (lane == 0) {
        out[row] = a;
        out[B_ * NE + row] = 1.0f;
    }
}

// ---------------------------------------------------------------------------
extern "C" void kernel_launch(void* const* d_in, const int* in_sizes, int n_in,
                              void* d_out, int out_size)
{
    const float* data = (const float*)d_in[0];
    const int*   cs   = (const int*)  d_in[1];
    const float* Wh1 = (const float*)d_in[3];
    const float* bh1 = (const float*)d_in[4];
    const float* Wh2 = (const float*)d_in[5];
    const float* bh2 = (const float*)d_in[6];
    const float* Wq1 = (const float*)d_in[7];
    const float* bq1 = (const float*)d_in[8];
    const float* Wq2 = (const float*)d_in[9];
    const float* bq2 = (const float*)d_in[10];
    const float* Wg1 = (const float*)d_in[11];
    const float* bg1 = (const float*)d_in[12];
    const float* Wg2 = (const float*)d_in[13];
    const float* bg2 = (const float*)d_in[14];
    const float* We1 = (const float*)d_in[15];
    const float* be1 = (const float*)d_in[16];
    const float* We2 = (const float*)d_in[17];
    float* out = (float*)d_out;

    float *p_Ah, *p_Aq, *p_WhT, *p_WqT, *p_xn, *p_hn1, *p_hn, *p_Hsum, *p_Qsum, *p_Hk2, *p_Q2;
    float *p_Hmat, *p_g1, *p_gs, *p_uu, *p_e1;
    cudaGetSymbolAddress((void**)&p_Ah, g_Ah);
    cudaGetSymbolAddress((void**)&p_Aq, g_Aq);
    cudaGetSymbolAddress((void**)&p_WhT, g_WhT);
    cudaGetSymbolAddress((void**)&p_WqT, g_WqT);
    cudaGetSymbolAddress((void**)&p_xn, g_xn);
    cudaGetSymbolAddress((void**)&p_hn1, g_hn1);
    cudaGetSymbolAddress((void**)&p_hn, g_hn);
    cudaGetSymbolAddress((void**)&p_Hsum, g_Hsum);
    cudaGetSymbolAddress((void**)&p_Qsum, g_Qsum);
    cudaGetSymbolAddress((void**)&p_Hk2, g_Hk2);
    cudaGetSymbolAddress((void**)&p_Q2, g_Q2);
    cudaGetSymbolAddress((void**)&p_Hmat, g_Hmat);
    cudaGetSymbolAddress((void**)&p_g1, g_g1);
    cudaGetSymbolAddress((void**)&p_gs, g_gs);
    cudaGetSymbolAddress((void**)&p_uu, g_uu);
    cudaGetSymbolAddress((void**)&p_e1, g_e1);

    static int smem_set = 0;
    if (!smem_set) {
        cudaFuncSetAttribute(tc_gemm, cudaFuncAttributeMaxDynamicSharedMemorySize, SMEM_GEMM);
        smem_set = 1;
    }

    // 0) sort clusters + gather x_n; transpose/round W for tensor cores
    k_setup<<<1, 256>>>(cs, data);
    k_prepW<<<(HD * XD + 255) / 256, 256>>>(Wh1, Wq1);

    // 1) first layer, h-region (tf32 mma.sync): tokens 0..2047 of every batch
    tc_gemm<<<dim3(NSEQ / BM, HD / BN, B_), 256, SMEM_GEMM>>>(
        data, p_WhT, bh1, p_Ah, NSEQ, (long long)NTOK * XD, (long long)NSEQ * HD);

    // 2) first layer, q-region: tokens 2049..4095 (2047 rows/batch)
    tc_gemm<<<dim3(NSEQ / BM, HD / BN, B_), 256, SMEM_GEMM>>>(
        data + (long long)(NSEQ + 1) * XD, p_WqT, bq1, p_Aq, NSEQ - 1,
        (long long)NTOK * XD, (long long)(NSEQ - 1) * HD);

    // 3) hn: full h-MLP for token n of each batch (exact fp32, tiny)
    sgemm<1, 1><<<dim3(HD / 128, 1, 1), 256>>>(p_xn, Wh1, bh1, p_hn1, B_, HD, XD, 0, 0);
    sgemm<0, 1><<<dim3(H2 / 128, 1, 1), 256>>>(p_hn1, Wh2, bh2, p_hn, B_, H2, HD, 0, 0);

    // 4) cluster sums + q sum
    k_reduce_h<<<dim3(KC, B_), 256>>>();
    k_reduce_q<<<dim3(16, B_), 512>>>();
    k_reduce_q2<<<B_, 512>>>();

    // 5) second layers on the summed activations
    sgemm<0, 0><<<dim3(H2 / 128, (B_ * KC) / 128, 1), 256>>>(
        p_Hsum, Wh2, nullptr, p_Hk2, B_ * KC, H2, HD, 0, 0);
    sgemm<0, 0><<<dim3(H2 / 128, 1, 1), 256>>>(
        p_Qsum, Wq2, nullptr, p_Q2, B_, H2, HD, 0, 0);

    // 6) build H rows, g-MLP
    k_buildH<<<dim3(NG, B_), H2>>>(bh2);
    sgemm<1, 1><<<dim3(HD / 128, (B_ * NG + 127) / 128, 1), 256>>>(
        p_Hmat, Wg1, bg1, p_g1, B_ * NG, HD, H2, 0, 0);
    sgemm<0, 1><<<dim3(GD / 128, (B_ * NG + 127) / 128, 1), 256>>>(
        p_g1, Wg2, bg2, p_gs, B_ * NG, GD, HD, 0, 0);

    // 7) S, uu, e-MLP, E + mask
    k_S<<<B_, GD>>>();
    k_builduu<<<dim3(NE, B_), 256>>>(bq2);
    sgemm<1, 1><<<dim3(HD / 128, (B_ * NE + 127) / 128, 1), 256>>>(
        p_uu, We1, be1, p_e1, B_ * NE, HD, GD + H2, 0, 0);
    k_E<<<(B_ * NE + 3) / 4, 128>>>(We2, out);
}

// round 5
// speedup vs baseline: 2.3545x; 1.1165x over previous
#include <cuda_runtime.h>
#include <cstdint>

// ---------------- problem constants (deterministic inputs) ----------------
#define B_    64
#define NTOK  4096
#define NSEQ  2048     // n
#define XD    256      // x_dim
#define HD    512      // Hd (hidden width)
#define H2    256      // h_dim
#define GD    512      // g_dim
#define KC    32       // clusters K
#define NG    65       // 2K+1
#define NE    33       // K+1

// ---------------- scratch (__device__ globals, no allocs) ----------------
__device__ float g_WhT [HD * XD];     // Wh1^T, tf32-rounded [512][256]
__device__ float g_WqT [HD * XD];     // Wq1^T, tf32-rounded [512][256]
__device__ float g_hn[B_ * H2];
__device__ float g_Hsum[B_ * KC * HD];
__device__ float g_Qsum[B_ * HD];
__device__ float g_Hk2[B_ * KC * H2];
__device__ float g_Q2[B_ * H2];
__device__ float g_Hmat[B_ * NG * H2];
__device__ float g_g1[B_ * NG * HD];
__device__ float g_gs[B_ * NG * GD];
__device__ float g_S[B_ * GD];
__device__ float g_uu[B_ * NE * (GD + H2)];
__device__ float g_e1[B_ * NE * HD];
__device__ int   g_tok[NSEQ];
__device__ int   g_cid[NSEQ];
__device__ int   g_cnt[KC];

// =======================================================================
//  tf32 mma.sync GEMM with fused reduction epilogue.
//  A fp32 row-major [M,K=256]. WT [N,K] row-major tf32-rounded.
//  CTA tile 128x128, 8 warps (2m x 4n), warp tile 64x32, BK=32,
//  3-stage cp.async. A fragments rna-rounded in registers.
//  MODE 1: rows gathered via tok[], epilogue = per-cluster column sums
//          (cid[] segments) atomicAdd into red[cluster*N + col].
//  MODE 2: epilogue = full column sum atomicAdd into red[col].
//  bias+relu applied per element before summing; grid.z = batch.
// =======================================================================
#define BM 128
#define BN 128
#define BK 32
#define STAGE_BYTES (BM * 128 + BN * 128)   // 32768
#define SMEM_GEMM (3 * STAGE_BYTES)         // 98304

__device__ __forceinline__ uint32_t s2u(const void* p) {
    uint32_t a;
    asm("{ .reg .u64 t; cvta.to.shared.u64 t, %1; cvt.u32.u64 %0, t; }" : "=r"(a) : "l"(p));
    return a;
}
__device__ __forceinline__ void cp16(uint32_t dst, const void* src, uint32_t sz) {
    asm volatile("cp.async.cg.shared.global [%0], [%1], 16, %2;\n" :: "r"(dst), "l"(src), "r"(sz));
}
__device__ __forceinline__ void cp_commit() {
    asm volatile("cp.async.commit_group;" ::: "memory");
}
template <int N>
__device__ __forceinline__ void cp_wait() {
    asm volatile("cp.async.wait_group %0;" :: "n"(N) : "memory");
}
__device__ __forceinline__ void ldsm4(uint32_t* r, uint32_t addr) {
    asm volatile("ldmatrix.sync.aligned.m8n8.x4.shared.b16 {%0,%1,%2,%3}, [%4];"
                 : "=r"(r[0]), "=r"(r[1]), "=r"(r[2]), "=r"(r[3]) : "r"(addr));
}
__device__ __forceinline__ void mma_tf32(float* d, const uint32_t* a, uint32_t b0, uint32_t b1) {
    asm volatile(
        "mma.sync.aligned.m16n8k8.row.col.f32.tf32.tf32.f32 "
        "{%0,%1,%2,%3}, {%4,%5,%6,%7}, {%8,%9}, {%0,%1,%2,%3};"
        : "+f"(d[0]), "+f"(d[1]), "+f"(d[2]), "+f"(d[3])
        : "r"(a[0]), "r"(a[1]), "r"(a[2]), "r"(a[3]), "r"(b0), "r"(b1));
}

template <int MODE>
__global__ __launch_bounds__(256, 2)
void tc_gemm_red(const float* __restrict__ A, const float* __restrict__ WT,
                 const float* __restrict__ bias,
                 int M, int N, int K,
                 long long strideA, float* __restrict__ red, long long strideRed,
                 const int* __restrict__ tok, const int* __restrict__ cid)
{
    extern __shared__ char smem[];
    const int tid = threadIdx.x, wid = tid >> 5, lane = tid & 31;
    const int warpM = wid & 1, warpN = wid >> 1;
    const int m0 = blockIdx.x * BM, n0 = blockIdx.y * BN;
    A += (long long)blockIdx.z * strideA;
    red += (long long)blockIdx.z * strideRed;
    const char* Ab = (const char*)A;
    const char* Bb = (const char*)WT;
    const uint32_t sb = s2u(smem);
    const int ldab = K * 4;
    const int nch = K / BK;

    // loader geometry (constant across chunks)
    uint32_t adst[4], bdst[4], asz[4];
    long long aoff[4], boff[4];
#pragma unroll
    for (int it = 0; it < 4; it++) {
        int g = it * 256 + tid, row = g >> 3, c16 = g & 7;
        uint32_t sw = ((uint32_t)(c16 ^ (row & 7))) << 4;
        adst[it] = (uint32_t)(row * 128) + sw;
        int lr = m0 + row;
        int valid = (lr < M);
        int grow = (MODE == 1) ? tok[valid ? lr : 0] : (valid ? lr : 0);
        asz[it] = valid ? 16u : 0u;
        aoff[it] = (long long)grow * ldab + c16 * 16;
        bdst[it] = (uint32_t)(BM * 128 + row * 128) + sw;
        boff[it] = (long long)(n0 + row) * ldab + c16 * 16;
    }

#define LOADC(c, stg) do {                                                  \
        uint32_t so_ = sb + (stg) * STAGE_BYTES;                           \
        _Pragma("unroll")                                                   \
        for (int it = 0; it < 4; it++)                                      \
            cp16(so_ + adst[it], Ab + aoff[it] + (c) * 128, asz[it]);       \
        _Pragma("unroll")                                                   \
        for (int it = 0; it < 4; it++)                                      \
            cp16(so_ + bdst[it], Bb + boff[it] + (c) * 128, 16u);           \
        cp_commit();                                                        \
    } while (0)

    float acc[4][4][4];
#pragma unroll
    for (int i = 0; i < 4; i++)
#pragma unroll
        for (int j = 0; j < 4; j++)
#pragma unroll
            for (int q = 0; q < 4; q++) acc[i][j][q] = 0.f;

    // ldmatrix per-lane geometry
    const int t = lane >> 3, r8 = lane & 7;
    int rowA[4];
#pragma unroll
    for (int mt = 0; mt < 4; mt++) rowA[mt] = warpM * 64 + mt * 16 + (t & 1) * 8 + r8;
    const int thalfA = t >> 1;
    int rowB[2];
#pragma unroll
    for (int p = 0; p < 2; p++) rowB[p] = warpN * 32 + p * 16 + (t >> 1) * 8 + r8;
    const int thalfB = t & 1;

    LOADC(0, 0);
    LOADC(1, 1);

    for (int c = 0; c < nch; c++) {
        if (c < nch - 1) cp_wait<1>(); else cp_wait<0>();
        __syncthreads();
        if (c + 2 < nch) LOADC(c + 2, (c + 2) % 3);

        const int stg = c % 3;
        const uint32_t as = sb + stg * STAGE_BYTES;
        const uint32_t bs = as + BM * 128;

#pragma unroll
        for (int kk = 0; kk < 4; kk++) {
            uint32_t af[4][4];
#pragma unroll
            for (int mt = 0; mt < 4; mt++) {
                uint32_t addr = as + rowA[mt] * 128 +
                                (((uint32_t)((kk * 2 + thalfA) ^ (rowA[mt] & 7))) << 4);
                ldsm4(af[mt], addr);
#pragma unroll
                for (int q = 0; q < 4; q++)
                    asm("cvt.rna.tf32.f32 %0, %0;" : "+r"(af[mt][q]));
            }
            uint32_t bf[2][4];
#pragma unroll
            for (int p = 0; p < 2; p++) {
                uint32_t addr = bs + rowB[p] * 128 +
                                (((uint32_t)((kk * 2 + thalfB) ^ (rowB[p] & 7))) << 4);
                ldsm4(bf[p], addr);
            }
#pragma unroll
            for (int mt = 0; mt < 4; mt++) {
#pragma unroll
                for (int nt = 0; nt < 4; nt++) {
                    const uint32_t* bp = bf[nt >> 1];
                    mma_tf32(acc[mt][nt], af[mt],
                             bp[(nt & 1) * 2], bp[(nt & 1) * 2 + 1]);
                }
            }
        }
    }
#undef LOADC

    // reduction epilogue: bias+relu into smem tile, segmented column sums
    const int g = lane >> 2, tig = lane & 3;
    __syncthreads();                       // stage buffers now reusable
    float* tile = (float*)smem;            // [128][pitch 129]
    int* scid = (int*)(smem + 128 * 129 * 4);
#pragma unroll
    for (int nt = 0; nt < 4; nt++) {
        int cl = warpN * 32 + nt * 8 + tig * 2;
        float2 bv = *(const float2*)(bias + n0 + cl);
#pragma unroll
        for (int mt = 0; mt < 4; mt++) {
            int r = warpM * 64 + mt * 16 + g;
            float v0 = fmaxf(acc[mt][nt][0] + bv.x, 0.f);
            float v1 = fmaxf(acc[mt][nt][1] + bv.y, 0.f);
            float v2 = fmaxf(acc[mt][nt][2] + bv.x, 0.f);
            float v3 = fmaxf(acc[mt][nt][3] + bv.y, 0.f);
            bool ok0 = (m0 + r < M), ok1 = (m0 + r + 8 < M);
            tile[r * 129 + cl]           = ok0 ? v0 : 0.f;
            tile[r * 129 + cl + 1]       = ok0 ? v1 : 0.f;
            tile[(r + 8) * 129 + cl]     = ok1 ? v2 : 0.f;
            tile[(r + 8) * 129 + cl + 1] = ok1 ? v3 : 0.f;
        }
    }
    if (MODE == 1 && tid < 128) {
        int lr = m0 + tid;
        scid[tid] = (lr < M) ? cid[lr] : 0;
    }
    __syncthreads();

    int c = tid & 127, half = tid >> 7, r0 = half * 64;
    if (MODE == 1) {
        float run = 0.f;
        int cur = scid[r0];
        for (int r = r0; r < r0 + 64; r++) {
            int k = scid[r];
            if (k != cur) {
                atomicAdd(&red[(long long)cur * N + n0 + c], run);
                run = 0.f; cur = k;
            }
            run += tile[r * 129 + c];
        }
        atomicAdd(&red[(long long)cur * N + n0 + c], run);
    } else {
        float run = 0.f;
        for (int r = r0; r < r0 + 64; r++) run += tile[r * 129 + c];
        atomicAdd(&red[n0 + c], run);
    }
}

// ------------- W transpose + tf32 rounding (Wh1, Wq1 only) -----------------
__global__ void k_prepW(const float* __restrict__ Wh1, const float* __restrict__ Wq1)
{
    int i = blockIdx.x * 256 + threadIdx.x;
    if (i < HD * XD) {
        int nn = i >> 8, kk = i & 255;
        uint32_t a, b;
        asm("cvt.rna.tf32.f32 %0, %1;" : "=r"(a) : "f"(Wh1[kk * HD + nn]));
        asm("cvt.rna.tf32.f32 %0, %1;" : "=r"(b) : "f"(Wq1[kk * HD + nn]));
        ((uint32_t*)g_WhT)[i] = a;
        ((uint32_t*)g_WqT)[i] = b;
    }
}

// ------------- zero accumulators ------------------------------------------
__global__ void k_zero()
{
    int i = blockIdx.x * 256 + threadIdx.x;
    if (i < B_ * KC * HD) g_Hsum[i] = 0.f;
    if (i < B_ * HD) g_Qsum[i] = 0.f;
}

// ------------- setup: counting-sort cs[0,:n] by cluster --------------------
__global__ void k_setup(const int* __restrict__ cs)
{
    __shared__ int scnt[KC];
    __shared__ int soff[KC];
    int tid = threadIdx.x;
    if (tid < KC) scnt[tid] = 0;
    __syncthreads();
    for (int t = tid; t < NSEQ; t += 256) atomicAdd(&scnt[cs[t]], 1);
    __syncthreads();
    if (tid == 0) {
        int acc = 0;
        for (int k = 0; k < KC; k++) {
            soff[k] = acc; g_cnt[k] = scnt[k];
            acc += scnt[k];
        }
    }
    __syncthreads();
    for (int t = tid; t < NSEQ; t += 256) {
        int cl = cs[t];
        int p = atomicAdd(&soff[cl], 1);
        g_tok[p] = t;
        g_cid[p] = cl;
    }
}

// ------------- hn: exact fp32 2-layer MLP for token n of each batch --------
__global__ __launch_bounds__(256)
void k_hn(const float* __restrict__ data, const float* __restrict__ Wh1,
          const float* __restrict__ bh1, const float* __restrict__ Wh2,
          const float* __restrict__ bh2)
{
    __shared__ float x[XD];
    __shared__ float h[HD];
    int b = blockIdx.x, tid = threadIdx.x;
    const float* xr = data + ((long long)b * NTOK + NSEQ) * XD;
    x[tid] = xr[tid];
    __syncthreads();
    float a0 = bh1[tid], a1 = bh1[tid + 256];
#pragma unroll 4
    for (int k = 0; k < XD; k++) {
        float xv = x[k];
        a0 = fmaf(xv, Wh1[k * HD + tid], a0);
        a1 = fmaf(xv, Wh1[k * HD + tid + 256], a1);
    }
    h[tid] = fmaxf(a0, 0.f);
    h[tid + 256] = fmaxf(a1, 0.f);
    __syncthreads();
    float a = bh2[tid];
#pragma unroll 4
    for (int k = 0; k < HD; k++) a = fmaf(h[k], Wh2[k * H2 + tid], a);
    g_hn[b * H2 + tid] = a;
}

// ---------------- generic fp32 tiled GEMM (exact, mid-size ops) ------------
template <int RELU, int HASBIAS>
__global__ __launch_bounds__(256, 2)
void sgemm(const float* __restrict__ A, const float* __restrict__ W,
           const float* __restrict__ bias, float* __restrict__ C,
           int M, int N, int K)
{
    __shared__ float As[16][128];
    __shared__ float Bs[16][128];

    const int tid = threadIdx.x;
    const int tx = tid & 15;
    const int ty = tid >> 4;
    const int n0 = blockIdx.x * 128;
    const int m0 = blockIdx.y * 128;

    float acc[8][8];
#pragma unroll
    for (int i = 0; i < 8; i++)
#pragma unroll
        for (int j = 0; j < 8; j++) acc[i][j] = 0.f;

    for (int k0 = 0; k0 < K; k0 += 16) {
#pragma unroll
        for (int it = 0; it < 2; it++) {
            int lin = it * 256 + tid;
            int m   = lin >> 2;
            int kq  = (lin & 3) * 4;
            float4 v = make_float4(0.f, 0.f, 0.f, 0.f);
            if (m0 + m < M)
                v = *(const float4*)(A + (long long)(m0 + m) * K + k0 + kq);
            As[kq + 0][m] = v.x; As[kq + 1][m] = v.y;
            As[kq + 2][m] = v.z; As[kq + 3][m] = v.w;
        }
#pragma unroll
        for (int it = 0; it < 2; it++) {
            int lin = it * 256 + tid;
            int k   = lin >> 5;
            int nq  = (lin & 31) * 4;
            *(float4*)&Bs[k][nq] =
                *(const float4*)(W + (long long)(k0 + k) * N + n0 + nq);
        }
        __syncthreads();

#pragma unroll
        for (int kk = 0; kk < 16; kk++) {
            float a[8], b[8];
            *(float4*)(a)     = *(float4*)&As[kk][ty * 8];
            *(float4*)(a + 4) = *(float4*)&As[kk][ty * 8 + 4];
            *(float4*)(b)     = *(float4*)&Bs[kk][tx * 8];
            *(float4*)(b + 4) = *(float4*)&Bs[kk][tx * 8 + 4];
#pragma unroll
            for (int i = 0; i < 8; i++)
#pragma unroll
                for (int j = 0; j < 8; j++)
                    acc[i][j] = fmaf(a[i], b[j], acc[i][j]);
        }
        __syncthreads();
    }

    float bi[8];
    if (HASBIAS) {
        *(float4*)(bi)     = *(const float4*)(bias + n0 + tx * 8);
        *(float4*)(bi + 4) = *(const float4*)(bias + n0 + tx * 8 + 4);
    }
#pragma unroll
    for (int i = 0; i < 8; i++) {
        int m = m0 + ty * 8 + i;
        if (m < M) {
            float out[8];
#pragma unroll
            for (int j = 0; j < 8; j++) {
                float v = acc[i][j];
                if (HASBIAS) v += bi[j];
                if (RELU) v = fmaxf(v, 0.f);
                out[j] = v;
            }
            float* cp = C + (long long)m * N + n0 + tx * 8;
            *(float4*)(cp)     = *(float4*)(out);
            *(float4*)(cp + 4) = *(float4*)(out + 4);
        }
    }
}

// ------------- build H matrix ---------------------------------------------
__global__ void k_buildH(const float* __restrict__ bh2)
{
    int i = blockIdx.x, b = blockIdx.y, j = threadIdx.x;
    float hnv = g_hn[b * H2 + j];
    float v;
    if (i < KC) {
        v = g_Hk2[(b * KC + i) * H2 + j] + (float)g_cnt[i] * bh2[j];
    } else if (i < 2 * KC) {
        int k = i - KC;
        v = g_Hk2[(b * KC + k) * H2 + j] + (float)g_cnt[k] * bh2[j] + hnv;
    } else {
        v = hnv;
    }
    g_Hmat[((long long)b * NG + i) * H2 + j] = v;
}

__global__ void k_S()
{
    int b = blockIdx.x, j = threadIdx.x;
    float a = 0.f;
    for (int k = 0; k < KC; k++) a += g_gs[((long long)b * NG + k) * GD + j];
    g_S[b * GD + j] = a;
}

__global__ void k_builduu(const float* __restrict__ bq2)
{
    int i = blockIdx.x, b = blockIdx.y, tid = threadIdx.x;
    long long row = (long long)b * NE + i;
    float* u = g_uu + row * (GD + H2);
    for (int j = tid; j < GD; j += 256) {
        float s = g_S[b * GD + j];
        float v;
        if (i < KC)
            v = s - g_gs[((long long)b * NG + i) * GD + j]
                  + g_gs[((long long)b * NG + KC + i) * GD + j];
        else
            v = s + g_gs[((long long)b * NG + 2 * KC) * GD + j];
        u[j] = v;
    }
    u[GD + tid] = g_Q2[b * H2 + tid] + 2047.0f * bq2[tid];
}

__global__ void k_E(const float* __restrict__ We2, float* __restrict__ out)
{
    int row = blockIdx.x * 4 + (threadIdx.x >> 5);
    int lane = threadIdx.x & 31;
    if (row >= B_ * NE) return;
    const float* e = g_e1 + (long long)row * HD;
    float a = 0.f;
    for (int j = lane; j < HD; j += 32) a += e[j] * We2[j];
#pragma unroll
    for (int o = 16; o > 0; o >>= 1) a += __shfl_xor_sync(0xFFFFFFFFu, a, o);
    if (lane == 0) {
        out[row] = a;
        out[B_ * NE + row] = 1.0f;
    }
}

// ---------------------------------------------------------------------------
extern "C" void kernel_launch(void* const* d_in, const int* in_sizes, int n_in,
                              void* d_out, int out_size)
{
    const float* data = (const float*)d_in[0];
    const int*   cs   = (const int*)  d_in[1];
    const float* Wh1 = (const float*)d_in[3];
    const float* bh1 = (const float*)d_in[4];
    const float* Wh2 = (const float*)d_in[5];
    const float* bh2 = (const float*)d_in[6];
    const float* Wq1 = (const float*)d_in[7];
    const float* bq1 = (const float*)d_in[8];
    const float* Wq2 = (const float*)d_in[9];
    const float* bq2 = (const float*)d_in[10];
    const float* Wg1 = (const float*)d_in[11];
    const float* bg1 = (const float*)d_in[12];
    const float* Wg2 = (const float*)d_in[13];
    const float* bg2 = (const float*)d_in[14];
    const float* We1 = (const float*)d_in[15];
    const float* be1 = (const float*)d_in[16];
    const float* We2 = (const float*)d_in[17];
    float* out = (float*)d_out;

    float *p_WhT, *p_WqT, *p_Hsum, *p_Qsum, *p_Hk2, *p_Q2;
    float *p_Hmat, *p_g1, *p_gs, *p_uu, *p_e1;
    int *p_tok, *p_cid;
    cudaGetSymbolAddress((void**)&p_WhT, g_WhT);
    cudaGetSymbolAddress((void**)&p_WqT, g_WqT);
    cudaGetSymbolAddress((void**)&p_Hsum, g_Hsum);
    cudaGetSymbolAddress((void**)&p_Qsum, g_Qsum);
    cudaGetSymbolAddress((void**)&p_Hk2, g_Hk2);
    cudaGetSymbolAddress((void**)&p_Q2, g_Q2);
    cudaGetSymbolAddress((void**)&p_Hmat, g_Hmat);
    cudaGetSymbolAddress((void**)&p_g1, g_g1);
    cudaGetSymbolAddress((void**)&p_gs, g_gs);
    cudaGetSymbolAddress((void**)&p_uu, g_uu);
    cudaGetSymbolAddress((void**)&p_e1, g_e1);
    cudaGetSymbolAddress((void**)&p_tok, g_tok);
    cudaGetSymbolAddress((void**)&p_cid, g_cid);

    static int smem_set = 0;
    if (!smem_set) {
        cudaFuncSetAttribute(tc_gemm_red<1>, cudaFuncAttributeMaxDynamicSharedMemorySize, SMEM_GEMM);
        cudaFuncSetAttribute(tc_gemm_red<2>, cudaFuncAttributeMaxDynamicSharedMemorySize, SMEM_GEMM);
        smem_set = 1;
    }

    // 0) setup, weight prep, accumulator zero
    k_setup<<<1, 256>>>(cs);
    k_prepW<<<(HD * XD + 255) / 256, 256>>>(Wh1, Wq1);
    k_zero<<<(B_ * KC * HD + 255) / 256, 256>>>();

    // 1) h first layer fused with cluster sums: Hsum[b,k,:]
    tc_gemm_red<1><<<dim3(NSEQ / BM, HD / BN, B_), 256, SMEM_GEMM>>>(
        data, p_WhT, bh1, NSEQ, HD, XD,
        (long long)NTOK * XD, p_Hsum, (long long)KC * HD, p_tok, p_cid);

    // 2) q first layer fused with total sum: Qsum[b,:] (tokens 2049..4095)
    tc_gemm_red<2><<<dim3(16, HD / BN, B_), 256, SMEM_GEMM>>>(
        data + (long long)(NSEQ + 1) * XD, p_WqT, bq1, NSEQ - 1, HD, XD,
        (long long)NTOK * XD, p_Qsum, (long long)HD, nullptr, nullptr);

    // 3) hn: exact fp32 2-layer MLP for token n
    k_hn<<<B_, 256>>>(data, Wh1, bh1, Wh2, bh2);

    // 4) second layers on the summed activations (exact fp32)
    sgemm<0, 0><<<dim3(H2 / 128, (B_ * KC) / 128, 1), 256>>>(
        p_Hsum, Wh2, nullptr, p_Hk2, B_ * KC, H2, HD);
    sgemm<0, 0><<<dim3(H2 / 128, 1, 1), 256>>>(
        p_Qsum, Wq2, nullptr, p_Q2, B_, H2, HD);

    // 5) build H rows, g-MLP (exact fp32)
    k_buildH<<<dim3(NG, B_), H2>>>(bh2);
    sgemm<1, 1><<<dim3(HD / 128, (B_ * NG + 127) / 128, 1), 256>>>(
        p_Hmat, Wg1, bg1, p_g1, B_ * NG, HD, H2);
    sgemm<0, 1><<<dim3(GD / 128, (B_ * NG + 127) / 128, 1), 256>>>(
        p_g1, Wg2, bg2, p_gs, B_ * NG, GD, HD);

    // 6) S, uu, e-MLP (exact fp32), E + mask
    k_S<<<B_, GD>>>();
    k_builduu<<<dim3(NE, B_), 256>>>(bq2);
    sgemm<1, 1><<<dim3(HD / 128, (B_ * NE + 127) / 128, 1), 256>>>(
        p_uu, We1, be1, p_e1, B_ * NE, HD, GD + H2);
    k_E<<<(B_ * NE + 3) / 4, 128>>>(We2, out);
}

// round 6
// speedup vs baseline: 2.4690x; 1.0486x over previous
#include <cuda_runtime.h>
#include <cstdint>

// ---------------- problem constants (deterministic inputs) ----------------
#define B_    64
#define NTOK  4096
#define NSEQ  2048     // n
#define XD    256      // x_dim
#define HD    512      // Hd (hidden width)
#define H2    256      // h_dim
#define GD    512      // g_dim
#define KC    32       // clusters K
#define NG    65       // 2K+1
#define NE    33       // K+1

// ---------------- scratch (__device__ globals, no allocs) ----------------
__device__ float g_WhT [HD * XD];     // Wh1^T, tf32-rounded [512][256]
__device__ float g_WqT [HD * XD];     // Wq1^T, tf32-rounded [512][256]
__device__ float g_hn[B_ * H2];
__device__ float g_Hsum[B_ * KC * HD];
__device__ float g_Qsum[B_ * HD];
__device__ float g_Hk2[B_ * KC * H2];
__device__ float g_Q2[B_ * H2];
__device__ float g_Hmat[B_ * NG * H2];
__device__ float g_g1[B_ * NG * HD];
__device__ float g_gs[B_ * NG * GD];
__device__ float g_S[B_ * GD];
__device__ float g_uu[B_ * NE * (GD + H2)];
__device__ float g_e1[B_ * NE * HD];
__device__ int   g_tok[NSEQ];
__device__ int   g_cid[NSEQ];
__device__ int   g_cnt[KC];

// =======================================================================
//  tf32 mma.sync GEMM with fused reduction epilogue.
//  A fp32 row-major [M,K=256]. WT [N,K] row-major tf32-rounded.
//  CTA tile 128x128, 8 warps in 4m x 2n (warp tile 32x64), BK=32,
//  3-stage cp.async. A fragments rna-rounded in registers.
//  MODE 1: rows gathered via tok[], epilogue = per-cluster column sums
//          (cid[] segments) atomicAdd into red[cluster*N + col].
//  MODE 2: epilogue = full column sum atomicAdd into red[col].
//  bias+relu applied per element before summing; grid.z = batch.
// =======================================================================
#define BM 128
#define BN 128
#define BK 32
#define STAGE_BYTES (BM * 128 + BN * 128)   // 32768
#define SMEM_GEMM (3 * STAGE_BYTES)         // 98304

__device__ __forceinline__ uint32_t s2u(const void* p) {
    uint32_t a;
    asm("{ .reg .u64 t; cvta.to.shared.u64 t, %1; cvt.u32.u64 %0, t; }" : "=r"(a) : "l"(p));
    return a;
}
__device__ __forceinline__ void cp16(uint32_t dst, const void* src, uint32_t sz) {
    asm volatile("cp.async.cg.shared.global [%0], [%1], 16, %2;\n" :: "r"(dst), "l"(src), "r"(sz));
}
__device__ __forceinline__ void cp_commit() {
    asm volatile("cp.async.commit_group;" ::: "memory");
}
template <int N>
__device__ __forceinline__ void cp_wait() {
    asm volatile("cp.async.wait_group %0;" :: "n"(N) : "memory");
}
__device__ __forceinline__ void ldsm4(uint32_t* r, uint32_t addr) {
    asm volatile("ldmatrix.sync.aligned.m8n8.x4.shared.b16 {%0,%1,%2,%3}, [%4];"
                 : "=r"(r[0]), "=r"(r[1]), "=r"(r[2]), "=r"(r[3]) : "r"(addr));
}
__device__ __forceinline__ void mma_tf32(float* d, const uint32_t* a, uint32_t b0, uint32_t b1) {
    asm volatile(
        "mma.sync.aligned.m16n8k8.row.col.f32.tf32.tf32.f32 "
        "{%0,%1,%2,%3}, {%4,%5,%6,%7}, {%8,%9}, {%0,%1,%2,%3};"
        : "+f"(d[0]), "+f"(d[1]), "+f"(d[2]), "+f"(d[3])
        : "r"(a[0]), "r"(a[1]), "r"(a[2]), "r"(a[3]), "r"(b0), "r"(b1));
}

template <int MODE>
__global__ __launch_bounds__(256, 2)
void tc_gemm_red(const float* __restrict__ A, const float* __restrict__ WT,
                 const float* __restrict__ bias,
                 int M, int N, int K,
                 long long strideA, float* __restrict__ red, long long strideRed,
                 const int* __restrict__ tok, const int* __restrict__ cid)
{
    extern __shared__ char smem[];
    const int tid = threadIdx.x, wid = tid >> 5, lane = tid & 31;
    const int warpM = wid & 3, warpN = wid >> 2;      // 4m x 2n
    const int m0 = blockIdx.x * BM, n0 = blockIdx.y * BN;
    A += (long long)blockIdx.z * strideA;
    red += (long long)blockIdx.z * strideRed;
    const char* Ab = (const char*)A;
    const char* Bb = (const char*)WT;
    const uint32_t sb = s2u(smem);
    const int ldab = K * 4;
    const int nch = K / BK;

    // loader geometry (constant across chunks)
    uint32_t adst[4], bdst[4], asz[4];
    long long aoff[4], boff[4];
#pragma unroll
    for (int it = 0; it < 4; it++) {
        int g = it * 256 + tid, row = g >> 3, c16 = g & 7;
        uint32_t sw = ((uint32_t)(c16 ^ (row & 7))) << 4;
        adst[it] = (uint32_t)(row * 128) + sw;
        int lr = m0 + row;
        int valid = (lr < M);
        int grow = (MODE == 1) ? tok[valid ? lr : 0] : (valid ? lr : 0);
        asz[it] = valid ? 16u : 0u;
        aoff[it] = (long long)grow * ldab + c16 * 16;
        bdst[it] = (uint32_t)(BM * 128 + row * 128) + sw;
        boff[it] = (long long)(n0 + row) * ldab + c16 * 16;
    }

#define LOADC(c, stg) do {                                                  \
        uint32_t so_ = sb + (stg) * STAGE_BYTES;                           \
        _Pragma("unroll")                                                   \
        for (int it = 0; it < 4; it++)                                      \
            cp16(so_ + adst[it], Ab + aoff[it] + (c) * 128, asz[it]);       \
        _Pragma("unroll")                                                   \
        for (int it = 0; it < 4; it++)                                      \
            cp16(so_ + bdst[it], Bb + boff[it] + (c) * 128, 16u);           \
        cp_commit();                                                        \
    } while (0)

    float acc[2][8][4];
#pragma unroll
    for (int i = 0; i < 2; i++)
#pragma unroll
        for (int j = 0; j < 8; j++)
#pragma unroll
            for (int q = 0; q < 4; q++) acc[i][j][q] = 0.f;

    // ldmatrix per-lane geometry
    const int t = lane >> 3, r8 = lane & 7;
    // A: per m16-tile x4 covers (rows0-7,kLo),(rows8-15,kLo),(rows0-7,kHi),(rows8-15,kHi)
    int rowA[2];
#pragma unroll
    for (int mt = 0; mt < 2; mt++) rowA[mt] = warpM * 32 + mt * 16 + (t & 1) * 8 + r8;
    const int thalfA = t >> 1;
    // B: per n16-pair x4 covers (n0-7,kLo),(n0-7,kHi),(n8-15,kLo),(n8-15,kHi)
    int rowB[4];
#pragma unroll
    for (int p = 0; p < 4; p++) rowB[p] = warpN * 64 + p * 16 + (t >> 1) * 8 + r8;
    const int thalfB = t & 1;

    LOADC(0, 0);
    LOADC(1, 1);

    for (int c = 0; c < nch; c++) {
        if (c < nch - 1) cp_wait<1>(); else cp_wait<0>();
        __syncthreads();
        if (c + 2 < nch) LOADC(c + 2, (c + 2) % 3);

        const int stg = c % 3;
        const uint32_t as = sb + stg * STAGE_BYTES;
        const uint32_t bs = as + BM * 128;

#pragma unroll
        for (int kk = 0; kk < 4; kk++) {
            uint32_t af[2][4];
#pragma unroll
            for (int mt = 0; mt < 2; mt++) {
                uint32_t addr = as + rowA[mt] * 128 +
                                (((uint32_t)((kk * 2 + thalfA) ^ (rowA[mt] & 7))) << 4);
                ldsm4(af[mt], addr);
#pragma unroll
                for (int q = 0; q < 4; q++)
                    asm("cvt.rna.tf32.f32 %0, %0;" : "+r"(af[mt][q]));
            }
            uint32_t bf[4][4];
#pragma unroll
            for (int p = 0; p < 4; p++) {
                uint32_t addr = bs + rowB[p] * 128 +
                                (((uint32_t)((kk * 2 + thalfB) ^ (rowB[p] & 7))) << 4);
                ldsm4(bf[p], addr);
            }
#pragma unroll
            for (int mt = 0; mt < 2; mt++) {
#pragma unroll
                for (int nt = 0; nt < 8; nt++) {
                    const uint32_t* bp = bf[nt >> 1];
                    mma_tf32(acc[mt][nt], af[mt],
                             bp[(nt & 1) * 2], bp[(nt & 1) * 2 + 1]);
                }
            }
        }
    }
#undef LOADC

    // reduction epilogue: bias+relu into smem tile, segmented column sums
    const int g = lane >> 2, tig = lane & 3;
    __syncthreads();                       // stage buffers now reusable
    float* tile = (float*)smem;            // [128][pitch 129]
    int* scid = (int*)(smem + 128 * 129 * 4);
#pragma unroll
    for (int nt = 0; nt < 8; nt++) {
        int cl = warpN * 64 + nt * 8 + tig * 2;
        float2 bv = *(const float2*)(bias + n0 + cl);
#pragma unroll
        for (int mt = 0; mt < 2; mt++) {
            int r = warpM * 32 + mt * 16 + g;
            float v0 = fmaxf(acc[mt][nt][0] + bv.x, 0.f);
            float v1 = fmaxf(acc[mt][nt][1] + bv.y, 0.f);
            float v2 = fmaxf(acc[mt][nt][2] + bv.x, 0.f);
            float v3 = fmaxf(acc[mt][nt][3] + bv.y, 0.f);
            bool ok0 = (m0 + r < M), ok1 = (m0 + r + 8 < M);
            tile[r * 129 + cl]           = ok0 ? v0 : 0.f;
            tile[r * 129 + cl + 1]       = ok0 ? v1 : 0.f;
            tile[(r + 8) * 129 + cl]     = ok1 ? v2 : 0.f;
            tile[(r + 8) * 129 + cl + 1] = ok1 ? v3 : 0.f;
        }
    }
    if (MODE == 1 && tid < 128) {
        int lr = m0 + tid;
        scid[tid] = (lr < M) ? cid[lr] : 0;
    }
    __syncthreads();

    int c = tid & 127, half = tid >> 7, r0 = half * 64;
    if (MODE == 1) {
        float run = 0.f;
        int cur = scid[r0];
        for (int r = r0; r < r0 + 64; r++) {
            int k = scid[r];
            if (k != cur) {
                atomicAdd(&red[(long long)cur * N + n0 + c], run);
                run = 0.f; cur = k;
            }
            run += tile[r * 129 + c];
        }
        atomicAdd(&red[(long long)cur * N + n0 + c], run);
    } else {
        float run = 0.f;
        for (int r = r0; r < r0 + 64; r++) run += tile[r * 129 + c];
        atomicAdd(&red[n0 + c], run);
    }
}

// ------------- W transpose + tf32 rounding (Wh1, Wq1 only) -----------------
__global__ void k_prepW(const float* __restrict__ Wh1, const float* __restrict__ Wq1)
{
    int i = blockIdx.x * 256 + threadIdx.x;
    if (i < HD * XD) {
        int nn = i >> 8, kk = i & 255;
        uint32_t a, b;
        asm("cvt.rna.tf32.f32 %0, %1;" : "=r"(a) : "f"(Wh1[kk * HD + nn]));
        asm("cvt.rna.tf32.f32 %0, %1;" : "=r"(b) : "f"(Wq1[kk * HD + nn]));
        ((uint32_t*)g_WhT)[i] = a;
        ((uint32_t*)g_WqT)[i] = b;
    }
}

// ------------- zero accumulators ------------------------------------------
__global__ void k_zero()
{
    int i = blockIdx.x * 256 + threadIdx.x;
    if (i < B_ * KC * HD) g_Hsum[i] = 0.f;
    if (i < B_ * HD) g_Qsum[i] = 0.f;
}

// ------------- setup: counting-sort cs[0,:n] by cluster --------------------
__global__ void k_setup(const int* __restrict__ cs)
{
    __shared__ int scnt[KC];
    __shared__ int soff[KC];
    int tid = threadIdx.x;
    if (tid < KC) scnt[tid] = 0;
    __syncthreads();
    for (int t = tid; t < NSEQ; t += 256) atomicAdd(&scnt[cs[t]], 1);
    __syncthreads();
    if (tid == 0) {
        int acc = 0;
        for (int k = 0; k < KC; k++) {
            soff[k] = acc; g_cnt[k] = scnt[k];
            acc += scnt[k];
        }
    }
    __syncthreads();
    for (int t = tid; t < NSEQ; t += 256) {
        int cl = cs[t];
        int p = atomicAdd(&soff[cl], 1);
        g_tok[p] = t;
        g_cid[p] = cl;
    }
}

// ------------- hn: exact fp32 2-layer MLP for token n of each batch --------
__global__ __launch_bounds__(256)
void k_hn(const float* __restrict__ data, const float* __restrict__ Wh1,
          const float* __restrict__ bh1, const float* __restrict__ Wh2,
          const float* __restrict__ bh2)
{
    __shared__ float x[XD];
    __shared__ float h[HD];
    int b = blockIdx.x, tid = threadIdx.x;
    const float* xr = data + ((long long)b * NTOK + NSEQ) * XD;
    x[tid] = xr[tid];
    __syncthreads();
    float a0 = bh1[tid], a1 = bh1[tid + 256];
#pragma unroll 4
    for (int k = 0; k < XD; k++) {
        float xv = x[k];
        a0 = fmaf(xv, Wh1[k * HD + tid], a0);
        a1 = fmaf(xv, Wh1[k * HD + tid + 256], a1);
    }
    h[tid] = fmaxf(a0, 0.f);
    h[tid + 256] = fmaxf(a1, 0.f);
    __syncthreads();
    float a = bh2[tid];
#pragma unroll 4
    for (int k = 0; k < HD; k++) a = fmaf(h[k], Wh2[k * H2 + tid], a);
    g_hn[b * H2 + tid] = a;
}

// ---------------- generic fp32 tiled GEMM (exact, mid-size ops) ------------
template <int RELU, int HASBIAS>
__global__ __launch_bounds__(256, 2)
void sgemm(const float* __restrict__ A, const float* __restrict__ W,
           const float* __restrict__ bias, float* __restrict__ C,
           int M, int N, int K)
{
    __shared__ float As[16][128];
    __shared__ float Bs[16][128];

    const int tid = threadIdx.x;
    const int tx = tid & 15;
    const int ty = tid >> 4;
    const int n0 = blockIdx.x * 128;
    const int m0 = blockIdx.y * 128;

    float acc[8][8];
#pragma unroll
    for (int i = 0; i < 8; i++)
#pragma unroll
        for (int j = 0; j < 8; j++) acc[i][j] = 0.f;

    for (int k0 = 0; k0 < K; k0 += 16) {
#pragma unroll
        for (int it = 0; it < 2; it++) {
            int lin = it * 256 + tid;
            int m   = lin >> 2;
            int kq  = (lin & 3) * 4;
            float4 v = make_float4(0.f, 0.f, 0.f, 0.f);
            if (m0 + m < M)
                v = *(const float4*)(A + (long long)(m0 + m) * K + k0 + kq);
            As[kq + 0][m] = v.x; As[kq + 1][m] = v.y;
            As[kq + 2][m] = v.z; As[kq + 3][m] = v.w;
        }
#pragma unroll
        for (int it = 0; it < 2; it++) {
            int lin = it * 256 + tid;
            int k   = lin >> 5;
            int nq  = (lin & 31) * 4;
            *(float4*)&Bs[k][nq] =
                *(const float4*)(W + (long long)(k0 + k) * N + n0 + nq);
        }
        __syncthreads();

#pragma unroll
        for (int kk = 0; kk < 16; kk++) {
            float a[8], b[8];
            *(float4*)(a)     = *(float4*)&As[kk][ty * 8];
            *(float4*)(a + 4) = *(float4*)&As[kk][ty * 8 + 4];
            *(float4*)(b)     = *(float4*)&Bs[kk][tx * 8];
            *(float4*)(b + 4) = *(float4*)&Bs[kk][tx * 8 + 4];
#pragma unroll
            for (int i = 0; i < 8; i++)
#pragma unroll
                for (int j = 0; j < 8; j++)
                    acc[i][j] = fmaf(a[i], b[j], acc[i][j]);
        }
        __syncthreads();
    }

    float bi[8];
    if (HASBIAS) {
        *(float4*)(bi)     = *(const float4*)(bias + n0 + tx * 8);
        *(float4*)(bi + 4) = *(const float4*)(bias + n0 + tx * 8 + 4);
    }
#pragma unroll
    for (int i = 0; i < 8; i++) {
        int m = m0 + ty * 8 + i;
        if (m < M) {
            float out[8];
#pragma unroll
            for (int j = 0; j < 8; j++) {
                float v = acc[i][j];
                if (HASBIAS) v += bi[j];
                if (RELU) v = fmaxf(v, 0.f);
                out[j] = v;
            }
            float* cp = C + (long long)m * N + n0 + tx * 8;
            *(float4*)(cp)     = *(float4*)(out);
            *(float4*)(cp + 4) = *(float4*)(out + 4);
        }
    }
}

// ------------- build H matrix ---------------------------------------------
__global__ void k_buildH(const float* __restrict__ bh2)
{
    int i = blockIdx.x, b = blockIdx.y, j = threadIdx.x;
    float hnv = g_hn[b * H2 + j];
    float v;
    if (i < KC) {
        v = g_Hk2[(b * KC + i) * H2 + j] + (float)g_cnt[i] * bh2[j];
    } else if (i < 2 * KC) {
        int k = i - KC;
        v = g_Hk2[(b * KC + k) * H2 + j] + (float)g_cnt[k] * bh2[j] + hnv;
    } else {
        v = hnv;
    }
    g_Hmat[((long long)b * NG + i) * H2 + j] = v;
}

__global__ void k_S()
{
    int b = blockIdx.x, j = threadIdx.x;
    float a = 0.f;
    for (int k = 0; k < KC; k++) a += g_gs[((long long)b * NG + k) * GD + j];
    g_S[b * GD + j] = a;
}

__global__ void k_builduu(const float* __restrict__ bq2)
{
    int i = blockIdx.x, b = blockIdx.y, tid = threadIdx.x;
    long long row = (long long)b * NE + i;
    float* u = g_uu + row * (GD + H2);
    for (int j = tid; j < GD; j += 256) {
        float s = g_S[b * GD + j];
        float v;
        if (i < KC)
            v = s - g_gs[((long long)b * NG + i) * GD + j]
                  + g_gs[((long long)b * NG + KC + i) * GD + j];
        else
            v = s + g_gs[((long long)b * NG + 2 * KC) * GD + j];
        u[j] = v;
    }
    u[GD + tid] = g_Q2[b * H2 + tid] + 2047.0f * bq2[tid];
}

__global__ void k_E(const float* __restrict__ We2, float* __restrict__ out)
{
    int row = blockIdx.x * 4 + (threadIdx.x >> 5);
    int lane = threadIdx.x & 31;
    if (row >= B_ * NE) return;
    const float* e = g_e1 + (long long)row * HD;
    float a = 0.f;
    for (int j = lane; j < HD; j += 32) a += e[j] * We2[j];
#pragma unroll
    for (int o = 16; o > 0; o >>= 1) a += __shfl_xor_sync(0xFFFFFFFFu, a, o);
    if (lane == 0) {
        out[row] = a;
        out[B_ * NE + row] = 1.0f;
    }
}

// ---------------------------------------------------------------------------
extern "C" void kernel_launch(void* const* d_in, const int* in_sizes, int n_in,
                              void* d_out, int out_size)
{
    const float* data = (const float*)d_in[0];
    const int*   cs   = (const int*)  d_in[1];
    const float* Wh1 = (const float*)d_in[3];
    const float* bh1 = (const float*)d_in[4];
    const float* Wh2 = (const float*)d_in[5];
    const float* bh2 = (const float*)d_in[6];
    const float* Wq1 = (const float*)d_in[7];
    const float* bq1 = (const float*)d_in[8];
    const float* Wq2 = (const float*)d_in[9];
    const float* bq2 = (const float*)d_in[10];
    const float* Wg1 = (const float*)d_in[11];
    const float* bg1 = (const float*)d_in[12];
    const float* Wg2 = (const float*)d_in[13];
    const float* bg2 = (const float*)d_in[14];
    const float* We1 = (const float*)d_in[15];
    const float* be1 = (const float*)d_in[16];
    const float* We2 = (const float*)d_in[17];
    float* out = (float*)d_out;

    float *p_WhT, *p_WqT, *p_Hsum, *p_Qsum, *p_Hk2, *p_Q2;
    float *p_Hmat, *p_g1, *p_gs, *p_uu, *p_e1;
    int *p_tok, *p_cid;
    cudaGetSymbolAddress((void**)&p_WhT, g_WhT);
    cudaGetSymbolAddress((void**)&p_WqT, g_WqT);
    cudaGetSymbolAddress((void**)&p_Hsum, g_Hsum);
    cudaGetSymbolAddress((void**)&p_Qsum, g_Qsum);
    cudaGetSymbolAddress((void**)&p_Hk2, g_Hk2);
    cudaGetSymbolAddress((void**)&p_Q2, g_Q2);
    cudaGetSymbolAddress((void**)&p_Hmat, g_Hmat);
    cudaGetSymbolAddress((void**)&p_g1, g_g1);
    cudaGetSymbolAddress((void**)&p_gs, g_gs);
    cudaGetSymbolAddress((void**)&p_uu, g_uu);
    cudaGetSymbolAddress((void**)&p_e1, g_e1);
    cudaGetSymbolAddress((void**)&p_tok, g_tok);
    cudaGetSymbolAddress((void**)&p_cid, g_cid);

    static int smem_set = 0;
    if (!smem_set) {
        cudaFuncSetAttribute(tc_gemm_red<1>, cudaFuncAttributeMaxDynamicSharedMemorySize, SMEM_GEMM);
        cudaFuncSetAttribute(tc_gemm_red<2>, cudaFuncAttributeMaxDynamicSharedMemorySize, SMEM_GEMM);
        smem_set = 1;
    }

    // 0) setup, weight prep, accumulator zero
    k_setup<<<1, 256>>>(cs);
    k_prepW<<<(HD * XD + 255) / 256, 256>>>(Wh1, Wq1);
    k_zero<<<(B_ * KC * HD + 255) / 256, 256>>>();

    // 1) h first layer fused with cluster sums: Hsum[b,k,:]
    tc_gemm_red<1><<<dim3(NSEQ / BM, HD / BN, B_), 256, SMEM_GEMM>>>(
        data, p_WhT, bh1, NSEQ, HD, XD,
        (long long)NTOK * XD, p_Hsum, (long long)KC * HD, p_tok, p_cid);

    // 2) q first layer fused with total sum: Qsum[b,:] (tokens 2049..4095)
    tc_gemm_red<2><<<dim3(16, HD / BN, B_), 256, SMEM_GEMM>>>(
        data + (long long)(NSEQ + 1) * XD, p_WqT, bq1, NSEQ - 1, HD, XD,
        (long long)NTOK * XD, p_Qsum, (long long)HD, nullptr, nullptr);

    // 3) hn: exact fp32 2-layer MLP for token n
    k_hn<<<B_, 256>>>(data, Wh1, bh1, Wh2, bh2);

    // 4) second layers on the summed activations (exact fp32)
    sgemm<0, 0><<<dim3(H2 / 128, (B_ * KC) / 128, 1), 256>>>(
        p_Hsum, Wh2, nullptr, p_Hk2, B_ * KC, H2, HD);
    sgemm<0, 0><<<dim3(H2 / 128, 1, 1), 256>>>(
        p_Qsum, Wq2, nullptr, p_Q2, B_, H2, HD);

    // 5) build H rows, g-MLP (exact fp32)
    k_buildH<<<dim3(NG, B_), H2>>>(bh2);
    sgemm<1, 1><<<dim3(HD / 128, (B_ * NG + 127) / 128, 1), 256>>>(
        p_Hmat, Wg1, bg1, p_g1, B_ * NG, HD, H2);
    sgemm<0, 1><<<dim3(GD / 128, (B_ * NG + 127) / 128, 1), 256>>>(
        p_g1, Wg2, bg2, p_gs, B_ * NG, GD, HD);

    // 6) S, uu, e-MLP (exact fp32), E + mask
    k_S<<<B_, GD>>>();
    k_builduu<<<dim3(NE, B_), 256>>>(bq2);
    sgemm<1, 1><<<dim3(HD / 128, (B_ * NE + 127) / 128, 1), 256>>>(
        p_uu, We1, be1, p_e1, B_ * NE, HD, GD + H2);
    k_E<<<(B_ * NE + 3) / 4, 128>>>(We2, out);
}